// round 16
// baseline (speedup 1.0000x reference)
#include <cuda_runtime.h>
#include <cuda_bf16.h>
#include <cuda_fp16.h>

#define NATOMS 50000
#define KNBR   32
#define EDGES  (NATOMS*KNBR)
#define HD     128
#define LNUM   6
#define GNUM   50
#define TPTS   8192
#define DMAXF  8.66045f
#define HGRID  (DMAXF / (float)(TPTS - 1))
#define TILE_STRIDE 136                    /* elements; 272B rows */
#define SMEM_2T (2*128*136*2)
#define SMEM_3T (3*128*136*2)
#define SX 64.0f
#define ST 128.0f
#define INV_SXT (1.0f/(64.0f*128.0f))

// ---------------- device scratch ----------------
__device__ float          g_h[NATOMS*HD];
__device__ unsigned char  g_x8[NATOMS*HD];
__device__ __nv_bfloat16  g_agg[NATOMS*HD];
__device__ unsigned char  g_t8[(size_t)LNUM*TPTS*HD];
__device__ __nv_bfloat16  g_U[(size_t)LNUM*TPTS*HD];
__device__ unsigned short g_gi[EDGES];
__device__ __nv_bfloat16  g_wT1[LNUM*HD*HD];
__device__ __nv_bfloat16  g_wT2[LNUM*HD*HD];
__device__ __nv_bfloat16  g_wTi[LNUM*HD*HD];
__device__ __nv_bfloat16  g_wM2[LNUM*HD*HD];

// ---------------- helpers ----------------
__device__ __forceinline__ float sspf(float x) {
    float u = 0.5f * x;
    float v = u * u;
    if (v <= 0.25f) {
        float p = fmaf(v, 31.f/14175.f, -17.f/2520.f);
        p = fmaf(v, p, 1.f/45.f);
        p = fmaf(v, p, -1.f/12.f);
        p = fmaf(v, p, 0.5f);
        return fmaf(v, p, u);
    }
    float ax = fabsf(x);
    return log1pf(__expf(-ax)) + fmaxf(x, 0.f) - 0.69314718056f;
}

__device__ __forceinline__ void mma_bf16(float c[4],
    unsigned a0, unsigned a1, unsigned a2, unsigned a3,
    unsigned b0, unsigned b1) {
    asm volatile(
        "mma.sync.aligned.m16n8k16.row.col.f32.bf16.bf16.f32 "
        "{%0,%1,%2,%3}, {%4,%5,%6,%7}, {%8,%9}, {%0,%1,%2,%3};\n"
        : "+f"(c[0]), "+f"(c[1]), "+f"(c[2]), "+f"(c[3])
        : "r"(a0), "r"(a1), "r"(a2), "r"(a3), "r"(b0), "r"(b1));
}

__device__ __forceinline__ void ldsm_x4(unsigned &r0, unsigned &r1, unsigned &r2, unsigned &r3,
                                        unsigned addr) {
    asm volatile("ldmatrix.sync.aligned.m8n8.x4.shared.b16 {%0,%1,%2,%3}, [%4];"
        : "=r"(r0), "=r"(r1), "=r"(r2), "=r"(r3) : "r"(addr));
}

// Warp-tile mainloop: rows mo..mo+31 x cols nbase..nbase+63 (M=32, N=64).
// acc[mi][nt] covers rows mo+mi*16.. x col nbase+nt*8. 21 FLOP per smem byte.
__device__ __forceinline__ void mma_warp32(unsigned sA, unsigned sB, int mo, int nbase, int lane,
                                           float acc[2][8][4]) {
    unsigned aOff0 = sA + (unsigned)(((mo + (lane & 15)) * TILE_STRIDE + 8 * (lane >> 4)) * 2);
    unsigned aOff1 = aOff0 + 16 * TILE_STRIDE * 2;
    unsigned bRow = (unsigned)(nbase + (lane >> 4) * 8 + (lane & 7));
    unsigned bOff = sB + (unsigned)((bRow * TILE_STRIDE + 8 * ((lane >> 3) & 1)) * 2);
    #pragma unroll
    for (int kt = 0; kt < 8; kt++) {
        unsigned a0, a1, a2, a3, a4, a5, a6, a7;
        ldsm_x4(a0, a1, a2, a3, aOff0 + kt * 32);
        ldsm_x4(a4, a5, a6, a7, aOff1 + kt * 32);
        #pragma unroll
        for (int np = 0; np < 4; np++) {
            unsigned b0, b1, b2, b3;
            ldsm_x4(b0, b1, b2, b3, bOff + np * (16 * TILE_STRIDE * 2) + kt * 32);
            mma_bf16(acc[0][2 * np],     a0, a1, a2, a3, b0, b1);
            mma_bf16(acc[0][2 * np + 1], a0, a1, a2, a3, b2, b3);
            mma_bf16(acc[1][2 * np],     a4, a5, a6, a7, b0, b1);
            mma_bf16(acc[1][2 * np + 1], a4, a5, a6, a7, b2, b3);
        }
    }
}

// ---- cp.async ----
__device__ __forceinline__ void cpa16(unsigned saddr, const void* g, unsigned srcsz) {
    asm volatile("cp.async.cg.shared.global [%0], [%1], 16, %2;"
                 :: "r"(saddr), "l"(g), "r"(srcsz));
}
__device__ __forceinline__ void cpa_commit() { asm volatile("cp.async.commit_group;"); }
template<int N> __device__ __forceinline__ void cpa_wait() {
    asm volatile("cp.async.wait_group %0;" :: "n"(N));
}
// 256-thread tile fill: 2 threads/row, 128B each.
__device__ __forceinline__ void cpa_fill(unsigned sDst, const __nv_bfloat16* src, int tid) {
    int r = tid >> 1, half = tid & 1;
    const char* s = (const char*)src + r * 256 + half * 128;
    unsigned d = sDst + (unsigned)(r * 272 + half * 128);
    #pragma unroll
    for (int j = 0; j < 8; j++) cpa16(d + j * 16, s + j * 16, 16);
}

__device__ __forceinline__ unsigned pack_bf16x2(float lo, float hi) {
    __nv_bfloat162 p = __floats2bfloat162_rn(lo, hi);
    return *reinterpret_cast<unsigned*>(&p);
}
__device__ __forceinline__ unsigned short e4m3x2_from_f2(float lo, float hi) {
    unsigned short r;
    asm("cvt.rn.satfinite.e4m3x2.f32 %0, %1, %2;" : "=h"(r) : "f"(hi), "f"(lo));
    return r;
}
__device__ __forceinline__ __half2 e4m3x2_to_h2(unsigned v) {
    unsigned r;
    asm("cvt.rn.f16x2.e4m3x2 %0, %1;" : "=r"(r) : "h"((unsigned short)v));
    return *reinterpret_cast<__half2*>(&r);
}

// Stage one ushort (fp8 cols c,c+1 of local row rloc) into staging (byte view of As).
__device__ __forceinline__ void stage_us2(char* stg, int rloc, int c, unsigned short u) {
    *reinterpret_cast<unsigned short*>(stg + rloc * 272 + c) = u;
}
// 256-thread flush of 128 staged rows (128B each) to global rows (stride 128B).
__device__ __forceinline__ void flush256(const char* stg, unsigned char* gdst, int row0,
                                         int tid, int nmax) {
    int fr = tid >> 1, q = tid & 1;
    int gr = row0 + fr;
    if (gr < nmax) {
        #pragma unroll
        for (int j = 0; j < 4; j++) {
            uint4 v = *reinterpret_cast<const uint4*>(stg + fr * 272 + q * 64 + j * 16);
            *reinterpret_cast<uint4*>(gdst + (size_t)gr * 128 + q * 64 + j * 16) = v;
        }
    }
}

// ---------------- prologue kernels ----------------

__global__ void u_kernel(const float* __restrict__ w1, const float* __restrict__ b1) {
    __shared__ float srbf[GNUM][64];
    int l = blockIdx.y, g0 = blockIdx.x * 64, f = threadIdx.x;
    float wreg[GNUM];
    #pragma unroll
    for (int j = 0; j < GNUM; j++) wreg[j] = w1[l * GNUM * HD + j * HD + f];
    const float DELTA = 10.f / 49.f;
    const float COEFF = -0.5f / (DELTA * DELTA);
    for (int i = f; i < 64 * GNUM; i += 128) {
        int j = i >> 6, g = i & 63;
        float d = (g0 + g) * HGRID;
        float u = d - j * DELTA;
        srbf[j][g] = __expf(COEFF * u * u);
    }
    __syncthreads();
    float sb = b1[l * HD + f];
    #pragma unroll 1
    for (int gt = 0; gt < 8; gt++) {
        float acc[8];
        #pragma unroll
        for (int q = 0; q < 8; q++) acc[q] = sb;
        #pragma unroll
        for (int j = 0; j < GNUM; j++) {
            const float4* p = reinterpret_cast<const float4*>(&srbf[j][gt * 8]);
            float4 r0 = p[0], r1 = p[1];
            acc[0] = fmaf(r0.x, wreg[j], acc[0]);
            acc[1] = fmaf(r0.y, wreg[j], acc[1]);
            acc[2] = fmaf(r0.z, wreg[j], acc[2]);
            acc[3] = fmaf(r0.w, wreg[j], acc[3]);
            acc[4] = fmaf(r1.x, wreg[j], acc[4]);
            acc[5] = fmaf(r1.y, wreg[j], acc[5]);
            acc[6] = fmaf(r1.z, wreg[j], acc[6]);
            acc[7] = fmaf(r1.w, wreg[j], acc[7]);
        }
        #pragma unroll
        for (int q = 0; q < 8; q++)
            g_U[((size_t)l * TPTS + g0 + gt * 8 + q) * HD + f] = __float2bfloat16(sspf(acc[q]));
    }
}

__global__ void wconv_kernel(const float* __restrict__ w1,
                             const float* __restrict__ w2,
                             const float* __restrict__ wi,
                             const float* __restrict__ m2) {
    int t = blockIdx.x * blockDim.x + threadIdx.x;
    const int per = LNUM * HD * HD;
    if (t >= 4 * per) return;
    int a = t / per, r = t - a * per;
    int l = r >> 14, q = r & 16383, n = q >> 7, k = q & 127;
    const float* src = (a == 0) ? w1 : (a == 1) ? w2 : (a == 2) ? wi : m2;
    float v = src[(l << 14) + (k << 7) + n];
    __nv_bfloat16* dst = (a == 0) ? g_wT1 : (a == 1) ? g_wT2 : (a == 2) ? g_wTi : g_wM2;
    dst[r] = __float2bfloat16(v);
}

// table8 = e4m3( (U @ w2 + b2) * C(d) * ST ) — 8 warps, M32xN64 warp tiles
__global__ __launch_bounds__(256, 2) void tableg_kernel(const float* __restrict__ b2) {
    extern __shared__ __nv_bfloat16 sm[];
    __nv_bfloat16* As = sm;
    __nv_bfloat16* Bs = sm + 128 * TILE_STRIDE;
    int tid = threadIdx.x;
    int warp = tid >> 5, lane = tid & 31, g = lane >> 2, t = lane & 3;
    int wm = warp & 3, wn = warp >> 2;
    int mo = wm * 32, nbase = wn * 64;
    int l = blockIdx.y, row0 = blockIdx.x * 128;
    unsigned sA = (unsigned)__cvta_generic_to_shared(As);
    unsigned sB = (unsigned)__cvta_generic_to_shared(Bs);
    cpa_fill(sA, g_U + ((size_t)l * TPTS + row0) * HD, tid);
    cpa_fill(sB, g_wM2 + l * HD * HD, tid);
    cpa_commit();
    cpa_wait<0>();
    __syncthreads();
    float acc[2][8][4];
    #pragma unroll
    for (int mi = 0; mi < 2; mi++)
        #pragma unroll
        for (int nt = 0; nt < 8; nt++) { acc[mi][nt][0]=acc[mi][nt][1]=acc[mi][nt][2]=acc[mi][nt][3]=0.f; }
    mma_warp32(sA, sB, mo, nbase, lane, acc);
    __syncthreads();   // all warps done reading As before staging into it
    char* stg = reinterpret_cast<char*>(As);
    #pragma unroll
    for (int mi = 0; mi < 2; mi++) {
        int r1 = row0 + mo + mi * 16 + g, r2 = r1 + 8;
        float C1 = 0.5f * (__cosf(r1 * HGRID * 0.3141592653589793f) + 1.f) * ST;
        float C2 = 0.5f * (__cosf(r2 * HGRID * 0.3141592653589793f) + 1.f) * ST;
        #pragma unroll
        for (int nt = 0; nt < 8; nt++) {
            int c = nbase + nt * 8 + 2 * t;
            float bb0 = b2[l * HD + c], bb1 = b2[l * HD + c + 1];
            stage_us2(stg, mo + mi*16 + g,     c, e4m3x2_from_f2((acc[mi][nt][0]+bb0)*C1, (acc[mi][nt][1]+bb1)*C1));
            stage_us2(stg, mo + mi*16 + g + 8, c, e4m3x2_from_f2((acc[mi][nt][2]+bb0)*C2, (acc[mi][nt][3]+bb1)*C2));
        }
    }
    __syncthreads();
    flush256(stg, g_t8 + (size_t)l * TPTS * HD, row0, tid, TPTS);
}

// x8 = e4m3( (emb[z] @ lin1_w[0]) * SX ), also g_h = emb[z].
__global__ __launch_bounds__(256, 2) void lin1embed_kernel(const int* __restrict__ z,
                                                           const float* __restrict__ emb) {
    extern __shared__ __nv_bfloat16 sm[];
    __nv_bfloat16* As = sm;
    __nv_bfloat16* Bs = sm + 128 * TILE_STRIDE;
    int tid = threadIdx.x;
    int warp = tid >> 5, lane = tid & 31, g = lane >> 2, t = lane & 3;
    int wm = warp & 3, wn = warp >> 2;
    int mo = wm * 32, nbase = wn * 64;
    int row0 = blockIdx.x * 128;
    unsigned sA = (unsigned)__cvta_generic_to_shared(As);
    unsigned sB = (unsigned)__cvta_generic_to_shared(Bs);
    cpa_fill(sB, g_wT1, tid);
    cpa_commit();
    {   // emb gather: 2 threads/row
        int r = tid >> 1, half = tid & 1;
        int gr = row0 + r;
        __nv_bfloat16* dstA = As + r * TILE_STRIDE + half * 64;
        if (gr < NATOMS) {
            int zr = z[gr];
            const float4* p = reinterpret_cast<const float4*>(emb + zr * HD + half * 64);
            float4 v[16];
            #pragma unroll
            for (int q = 0; q < 16; q++) v[q] = p[q];
            float4* dh = reinterpret_cast<float4*>(g_h + (size_t)gr * HD + half * 64);
            #pragma unroll
            for (int q = 0; q < 16; q++) {
                dh[q] = v[q];
                uint2 st;
                st.x = pack_bf16x2(v[q].x, v[q].y);
                st.y = pack_bf16x2(v[q].z, v[q].w);
                *reinterpret_cast<uint2*>(dstA + q * 4) = st;
            }
        } else {
            #pragma unroll
            for (int q = 0; q < 16; q++)
                *reinterpret_cast<uint2*>(dstA + q * 4) = make_uint2(0u, 0u);
        }
    }
    cpa_wait<0>();
    __syncthreads();
    float acc[2][8][4];
    #pragma unroll
    for (int mi = 0; mi < 2; mi++)
        #pragma unroll
        for (int nt = 0; nt < 8; nt++) { acc[mi][nt][0]=acc[mi][nt][1]=acc[mi][nt][2]=acc[mi][nt][3]=0.f; }
    mma_warp32(sA, sB, mo, nbase, lane, acc);
    __syncthreads();
    char* stg = reinterpret_cast<char*>(As);
    #pragma unroll
    for (int mi = 0; mi < 2; mi++) {
        #pragma unroll
        for (int nt = 0; nt < 8; nt++) {
            int c = nbase + nt * 8 + 2 * t;
            stage_us2(stg, mo + mi*16 + g,     c, e4m3x2_from_f2(acc[mi][nt][0]*SX, acc[mi][nt][1]*SX));
            stage_us2(stg, mo + mi*16 + g + 8, c, e4m3x2_from_f2(acc[mi][nt][2]*SX, acc[mi][nt][3]*SX));
        }
    }
    __syncthreads();
    flush256(stg, g_x8, row0, tid, NATOMS);
}

__global__ void eprep_kernel(const float* __restrict__ pos, const int* __restrict__ col) {
    int e = blockIdx.x * blockDim.x + threadIdx.x;
    if (e >= EDGES) return;
    int r = e >> 5;
    int c = col[e];
    float dx = pos[3*r]   - pos[3*c];
    float dy = pos[3*r+1] - pos[3*c+1];
    float dz = pos[3*r+2] - pos[3*c+2];
    float d = sqrtf(fmaf(dx, dx, fmaf(dy, dy, dz * dz)));
    int gi = __float2int_rn(d * (1.0f / HGRID));
    gi = max(0, min(TPTS - 1, gi));
    g_gi[e] = (unsigned short)gi;
}

// ---------------- per-layer kernels ----------------

// High-occupancy standalone edge gather (saturates L2).
__global__ void edge_agg_kernel(const int* __restrict__ col, int l) {
    int warp = threadIdx.x >> 5, lane = threadIdx.x & 31;
    int atom = blockIdx.x * 8 + warp;
    if (atom >= NATOMS) return;
    int base = atom * KNBR;
    int cIdx = col[base + lane];
    int gIdx = (int)g_gi[base + lane];
    const unsigned char* tab = g_t8 + (size_t)l * TPTS * HD;
    __half2 a01 = __floats2half2_rn(0.f, 0.f);
    __half2 a23 = __floats2half2_rn(0.f, 0.f);
    int off = lane * 4;
    #pragma unroll 8
    for (int k = 0; k < KNBR; k++) {
        int c  = __shfl_sync(0xffffffffu, cIdx, k);
        int gg = __shfl_sync(0xffffffffu, gIdx, k);
        unsigned xw = *reinterpret_cast<const unsigned*>(g_x8 + c * HD + off);
        unsigned tw = *reinterpret_cast<const unsigned*>(tab + gg * HD + off);
        a01 = __hfma2(e4m3x2_to_h2(xw), e4m3x2_to_h2(tw), a01);
        a23 = __hfma2(e4m3x2_to_h2(xw >> 16), e4m3x2_to_h2(tw >> 16), a23);
    }
    float2 f01 = __half22float2(a01);
    float2 f23 = __half22float2(a23);
    uint2 out;
    out.x = pack_bf16x2(f01.x * INV_SXT, f01.y * INV_SXT);
    out.y = pack_bf16x2(f23.x * INV_SXT, f23.y * INV_SXT);
    *reinterpret_cast<uint2*>(&g_agg[atom * HD + off]) = out;
}

// h += ssp(agg @ lin2 + b2) @ int_lin + bi ; x8 = e4m3(h_new @ W1[l+1] * SX).
__global__ __launch_bounds__(256, 2) void fusedX_kernel(int l, const float* __restrict__ b2,
                                                        const float* __restrict__ bi) {
    extern __shared__ __nv_bfloat16 sm[];
    __nv_bfloat16* As  = sm;
    __nv_bfloat16* Bs  = sm + 128 * TILE_STRIDE;
    __nv_bfloat16* Bs2 = sm + 2 * 128 * TILE_STRIDE;
    int tid = threadIdx.x;
    int warp = tid >> 5, lane = tid & 31, g = lane >> 2, t = lane & 3;
    int wm = warp & 3, wn = warp >> 2;
    int mo = wm * 32, nbase = wn * 64;
    int row0 = blockIdx.x * 128;
    unsigned sA  = (unsigned)__cvta_generic_to_shared(As);
    unsigned sB  = (unsigned)__cvta_generic_to_shared(Bs);
    unsigned sB2 = (unsigned)__cvta_generic_to_shared(Bs2);
    // group0: As (agg, zfill-guarded) + Bs (W2) + Bs2 (Wi)
    {
        int r = tid >> 1, half = tid & 1;
        int gr = row0 + r;
        unsigned sz = (gr < NATOMS) ? 16u : 0u;
        const char* srcA = (const char*)(g_agg + (size_t)(gr < NATOMS ? gr : 0) * HD) + half * 128;
        unsigned dA = sA + (unsigned)(r * 272 + half * 128);
        #pragma unroll
        for (int j = 0; j < 8; j++) cpa16(dA + j * 16, srcA + j * 16, sz);
    }
    cpa_fill(sB,  g_wT2 + l * HD * HD, tid);
    cpa_fill(sB2, g_wTi + l * HD * HD, tid);
    cpa_commit();
    cpa_wait<0>();
    __syncthreads();
    float acc[2][8][4];
    #pragma unroll
    for (int mi = 0; mi < 2; mi++)
        #pragma unroll
        for (int nt = 0; nt < 8; nt++) { acc[mi][nt][0]=acc[mi][nt][1]=acc[mi][nt][2]=acc[mi][nt][3]=0.f; }
    // ---- stage 1: agg @ lin2 ----
    mma_warp32(sA, sB, mo, nbase, lane, acc);
    __syncthreads();           // all warps done reading As + Bs
    // ssp(+bias) -> As
    #pragma unroll
    for (int mi = 0; mi < 2; mi++) {
        #pragma unroll
        for (int nt = 0; nt < 8; nt++) {
            int c = nbase + nt * 8 + 2 * t;
            float v0 = sspf(acc[mi][nt][0] + b2[c]);
            float v1 = sspf(acc[mi][nt][1] + b2[c + 1]);
            float v2 = sspf(acc[mi][nt][2] + b2[c]);
            float v3 = sspf(acc[mi][nt][3] + b2[c + 1]);
            *reinterpret_cast<unsigned*>(&As[(mo+mi*16+g)  *TILE_STRIDE + c]) = pack_bf16x2(v0, v1);
            *reinterpret_cast<unsigned*>(&As[(mo+mi*16+g+8)*TILE_STRIDE + c]) = pack_bf16x2(v2, v3);
        }
    }
    __syncthreads();
    if (l < LNUM - 1) {        // group1: W1next streams in during stage 2
        cpa_fill(sB, g_wT1 + (l + 1) * HD * HD, tid);
        cpa_commit();
    }
    // ---- stage 2: t @ int_lin ----
    #pragma unroll
    for (int mi = 0; mi < 2; mi++)
        #pragma unroll
        for (int nt = 0; nt < 8; nt++) { acc[mi][nt][0]=acc[mi][nt][1]=acc[mi][nt][2]=acc[mi][nt][3]=0.f; }
    mma_warp32(sA, sB2, mo, nbase, lane, acc);
    __syncthreads();           // all warps done reading As before rewriting it
    #pragma unroll
    for (int mi = 0; mi < 2; mi++) {
        int r1 = row0 + mo + mi * 16 + g, r2 = r1 + 8;
        #pragma unroll
        for (int nt = 0; nt < 8; nt++) {
            int c = nbase + nt * 8 + 2 * t;
            float bb0 = bi[c], bb1 = bi[c + 1];
            if (r1 < NATOMS) {
                float2 hv = *reinterpret_cast<float2*>(&g_h[r1 * HD + c]);
                hv.x += acc[mi][nt][0] + bb0;
                hv.y += acc[mi][nt][1] + bb1;
                *reinterpret_cast<float2*>(&g_h[r1 * HD + c]) = hv;
                *reinterpret_cast<unsigned*>(&As[(mo+mi*16+g)*TILE_STRIDE + c]) = pack_bf16x2(hv.x, hv.y);
            } else {
                *reinterpret_cast<unsigned*>(&As[(mo+mi*16+g)*TILE_STRIDE + c]) = 0u;
            }
            if (r2 < NATOMS) {
                float2 hv = *reinterpret_cast<float2*>(&g_h[r2 * HD + c]);
                hv.x += acc[mi][nt][2] + bb0;
                hv.y += acc[mi][nt][3] + bb1;
                *reinterpret_cast<float2*>(&g_h[r2 * HD + c]) = hv;
                *reinterpret_cast<unsigned*>(&As[(mo+mi*16+g+8)*TILE_STRIDE + c]) = pack_bf16x2(hv.x, hv.y);
            } else {
                *reinterpret_cast<unsigned*>(&As[(mo+mi*16+g+8)*TILE_STRIDE + c]) = 0u;
            }
        }
    }
    cpa_wait<0>();             // W1next complete (no-op on last layer)
    if (l >= LNUM - 1) return;
    __syncthreads();           // As writes + Bs(W1next) visible to all
    // ---- stage 3: x8 = h_new @ W1[l+1] ----
    #pragma unroll
    for (int mi = 0; mi < 2; mi++)
        #pragma unroll
        for (int nt = 0; nt < 8; nt++) { acc[mi][nt][0]=acc[mi][nt][1]=acc[mi][nt][2]=acc[mi][nt][3]=0.f; }
    mma_warp32(sA, sB, mo, nbase, lane, acc);
    __syncthreads();           // all warps done reading As before staging
    char* stg = reinterpret_cast<char*>(As);
    #pragma unroll
    for (int mi = 0; mi < 2; mi++) {
        #pragma unroll
        for (int nt = 0; nt < 8; nt++) {
            int c = nbase + nt * 8 + 2 * t;
            stage_us2(stg, mo + mi*16 + g,     c, e4m3x2_from_f2(acc[mi][nt][0]*SX, acc[mi][nt][1]*SX));
            stage_us2(stg, mo + mi*16 + g + 8, c, e4m3x2_from_f2(acc[mi][nt][2]*SX, acc[mi][nt][3]*SX));
        }
    }
    __syncthreads();
    flush256(stg, g_x8, row0, tid, NATOMS);
}

// ---------------- head ----------------
__global__ void head_kernel(const float* __restrict__ w1, const float* __restrict__ b1, const float* __restrict__ a1p,
                            const float* __restrict__ w2, const float* __restrict__ b2, const float* __restrict__ a2p,
                            const float* __restrict__ w3, const float* __restrict__ b3,
                            float* __restrict__ out) {
    int warp = threadIdx.x >> 5, lane = threadIdx.x & 31;
    int atom = blockIdx.x * 8 + warp;
    if (atom >= NATOMS) return;
    float hh[4];
    #pragma unroll
    for (int q = 0; q < 4; q++) hh[q] = g_h[atom * HD + q * 32 + lane];
    float s1a = b1[lane], s1b = b1[lane + 32];
    #pragma unroll
    for (int q = 0; q < 4; q++) {
        #pragma unroll 8
        for (int k2 = 0; k2 < 32; k2++) {
            float hv = __shfl_sync(0xffffffffu, hh[q], k2);
            int k = q * 32 + k2;
            s1a = fmaf(hv, w1[k * 64 + lane], s1a);
            s1b = fmaf(hv, w1[k * 64 + lane + 32], s1b);
        }
    }
    float A1 = a1p[0];
    float t1a = (s1a >= 0.f) ? s1a : A1 * s1a;
    float t1b = (s1b >= 0.f) ? s1b : A1 * s1b;
    float s2 = b2[lane];
    #pragma unroll
    for (int q = 0; q < 2; q++) {
        float src = q ? t1b : t1a;
        #pragma unroll 8
        for (int j2 = 0; j2 < 32; j2++) {
            float tv = __shfl_sync(0xffffffffu, src, j2);
            s2 = fmaf(tv, w2[(q * 32 + j2) * 32 + lane], s2);
        }
    }
    float A2 = a2p[0];
    float t2 = (s2 >= 0.f) ? s2 : A2 * s2;
    float p = t2 * w3[lane];
    #pragma unroll
    for (int o = 16; o > 0; o >>= 1) p += __shfl_xor_sync(0xffffffffu, p, o);
    if (lane == 0) out[atom] = p + b3[0];
}

// ---------------- launch ----------------
extern "C" void kernel_launch(void* const* d_in, const int* in_sizes, int n_in,
                              void* d_out, int out_size) {
    const int*   z    = (const int*)  d_in[0];
    const float* pos  = (const float*)d_in[1];
    const int*   eidx = (const int*)  d_in[2];
    const float* emb  = (const float*)d_in[3];
    const float* mw1  = (const float*)d_in[4];
    const float* mb1  = (const float*)d_in[5];
    const float* mw2  = (const float*)d_in[6];
    const float* mb2  = (const float*)d_in[7];
    const float* l1w  = (const float*)d_in[8];
    const float* l2w  = (const float*)d_in[9];
    const float* l2b  = (const float*)d_in[10];
    const float* ilw  = (const float*)d_in[11];
    const float* ilb  = (const float*)d_in[12];
    const float* hw1  = (const float*)d_in[13];
    const float* hb1  = (const float*)d_in[14];
    const float* ha1  = (const float*)d_in[15];
    const float* hw2  = (const float*)d_in[16];
    const float* hb2  = (const float*)d_in[17];
    const float* ha2  = (const float*)d_in[18];
    const float* hw3  = (const float*)d_in[19];
    const float* hb3  = (const float*)d_in[20];
    const int*   col  = eidx + EDGES;
    float*       out  = (float*)d_out;

    static int smem_set = 0;
    if (!smem_set) {
        cudaFuncSetAttribute(lin1embed_kernel, cudaFuncAttributeMaxDynamicSharedMemorySize, SMEM_2T);
        cudaFuncSetAttribute(tableg_kernel,    cudaFuncAttributeMaxDynamicSharedMemorySize, SMEM_2T);
        cudaFuncSetAttribute(fusedX_kernel,    cudaFuncAttributeMaxDynamicSharedMemorySize, SMEM_3T);
        smem_set = 1;
    }

    int gemm_blocks = (NATOMS + 127) / 128;
    int atom_blocks = (NATOMS + 7) / 8;

    // ncu capture (4th launch) stays on lin1embed.
    u_kernel<<<dim3(TPTS / 64, LNUM), 128>>>(mw1, mb1);                          // 0
    wconv_kernel<<<(4 * LNUM * HD * HD + 255) / 256, 256>>>(l1w, l2w, ilw, mw2); // 1
    tableg_kernel<<<dim3(TPTS / 128, LNUM), 256, SMEM_2T>>>(mb2);                // 2
    lin1embed_kernel<<<gemm_blocks, 256, SMEM_2T>>>(z, emb);                     // 3  <-- profiled
    eprep_kernel<<<(EDGES + 255) / 256, 256>>>(pos, col);                        // 4

    for (int l = 0; l < LNUM; l++) {
        edge_agg_kernel<<<atom_blocks, 256>>>(col, l);
        fusedX_kernel<<<gemm_blocks, 256, SMEM_3T>>>(l, l2b + l * HD, ilb + l * HD);
    }
    head_kernel<<<atom_blocks, 256>>>(hw1, hb1, ha1, hw2, hb2, ha2, hw3, hb3, out);
}

// round 17
// speedup vs baseline: 1.1438x; 1.1438x over previous
#include <cuda_runtime.h>
#include <cuda_bf16.h>
#include <cuda_fp16.h>

#define NATOMS 50000
#define KNBR   32
#define EDGES  (NATOMS*KNBR)
#define HD     128
#define LNUM   6
#define GNUM   50
#define TPTS   8192
#define DMAXF  8.66045f
#define HGRID  (DMAXF / (float)(TPTS - 1))
#define TILE_STRIDE 136                    /* elements; 272B rows */
#define SMEM_2T (2*128*136*2)
#define SMEM_3T (3*128*136*2)
#define SX 64.0f
#define ST 128.0f
#define INV_SXT (1.0f/(64.0f*128.0f))

// ---------------- device scratch ----------------
__device__ float          g_h[NATOMS*HD];
__device__ unsigned char  g_x8[NATOMS*HD];
__device__ __nv_bfloat16  g_agg[NATOMS*HD];
__device__ unsigned char  g_t8[(size_t)LNUM*TPTS*HD];
__device__ __nv_bfloat16  g_U[(size_t)LNUM*TPTS*HD];
__device__ unsigned short g_gi[EDGES];
__device__ __nv_bfloat16  g_wT1[LNUM*HD*HD];
__device__ __nv_bfloat16  g_wT2[LNUM*HD*HD];
__device__ __nv_bfloat16  g_wTi[LNUM*HD*HD];
__device__ __nv_bfloat16  g_wM2[LNUM*HD*HD];

// ---------------- helpers ----------------
__device__ __forceinline__ float sspf(float x) {
    float u = 0.5f * x;
    float v = u * u;
    if (v <= 0.25f) {
        float p = fmaf(v, 31.f/14175.f, -17.f/2520.f);
        p = fmaf(v, p, 1.f/45.f);
        p = fmaf(v, p, -1.f/12.f);
        p = fmaf(v, p, 0.5f);
        return fmaf(v, p, u);
    }
    float ax = fabsf(x);
    return log1pf(__expf(-ax)) + fmaxf(x, 0.f) - 0.69314718056f;
}

__device__ __forceinline__ void mma_bf16(float c[4],
    unsigned a0, unsigned a1, unsigned a2, unsigned a3,
    unsigned b0, unsigned b1) {
    asm volatile(
        "mma.sync.aligned.m16n8k16.row.col.f32.bf16.bf16.f32 "
        "{%0,%1,%2,%3}, {%4,%5,%6,%7}, {%8,%9}, {%0,%1,%2,%3};\n"
        : "+f"(c[0]), "+f"(c[1]), "+f"(c[2]), "+f"(c[3])
        : "r"(a0), "r"(a1), "r"(a2), "r"(a3), "r"(b0), "r"(b1));
}

__device__ __forceinline__ void ldsm_x4(unsigned &r0, unsigned &r1, unsigned &r2, unsigned &r3,
                                        unsigned addr) {
    asm volatile("ldmatrix.sync.aligned.m8n8.x4.shared.b16 {%0,%1,%2,%3}, [%4];"
        : "=r"(r0), "=r"(r1), "=r"(r2), "=r"(r3) : "r"(addr));
}

// Half-tile mainloop: warp computes rows mo..mo+15 x cols nbase..nbase+63.
__device__ __forceinline__ void mma_half(unsigned sA, unsigned sB, int mo, int nbase, int lane,
                                         float acc[8][4]) {
    unsigned aOff = sA + (unsigned)(((mo + (lane & 15)) * TILE_STRIDE + 8 * (lane >> 4)) * 2);
    unsigned bRow = (unsigned)(nbase + (lane >> 4) * 8 + (lane & 7));
    unsigned bOff = sB + (unsigned)((bRow * TILE_STRIDE + 8 * ((lane >> 3) & 1)) * 2);
    #pragma unroll
    for (int kt = 0; kt < 8; kt++) {
        unsigned a0, a1, a2, a3;
        ldsm_x4(a0, a1, a2, a3, aOff + kt * 32);
        #pragma unroll
        for (int np = 0; np < 4; np++) {
            unsigned b0, b1, b2, b3;
            ldsm_x4(b0, b1, b2, b3, bOff + np * (16 * TILE_STRIDE * 2) + kt * 32);
            mma_bf16(acc[2 * np],     a0, a1, a2, a3, b0, b1);
            mma_bf16(acc[2 * np + 1], a0, a1, a2, a3, b2, b3);
        }
    }
}

// ---- cp.async ----
__device__ __forceinline__ void cpa16(unsigned saddr, const void* g, unsigned srcsz) {
    asm volatile("cp.async.cg.shared.global [%0], [%1], 16, %2;"
                 :: "r"(saddr), "l"(g), "r"(srcsz));
}
__device__ __forceinline__ void cpa_commit() { asm volatile("cp.async.commit_group;"); }
template<int N> __device__ __forceinline__ void cpa_wait() {
    asm volatile("cp.async.wait_group %0;" :: "n"(N));
}
// 512-thread tile fill: 4 threads/row, 64B each.
__device__ __forceinline__ void cpa_fill512(unsigned sDst, const __nv_bfloat16* src, int tid) {
    int r = tid >> 2, q = tid & 3;
    const char* s = (const char*)src + r * 256 + q * 64;
    unsigned d = sDst + (unsigned)(r * 272 + q * 64);
    #pragma unroll
    for (int j = 0; j < 4; j++) cpa16(d + j * 16, s + j * 16, 16);
}

__device__ __forceinline__ unsigned pack_bf16x2(float lo, float hi) {
    __nv_bfloat162 p = __floats2bfloat162_rn(lo, hi);
    return *reinterpret_cast<unsigned*>(&p);
}
__device__ __forceinline__ unsigned short e4m3x2_from_f2(float lo, float hi) {
    unsigned short r;
    asm("cvt.rn.satfinite.e4m3x2.f32 %0, %1, %2;" : "=h"(r) : "f"(hi), "f"(lo));
    return r;
}
__device__ __forceinline__ __half2 e4m3x2_to_h2(unsigned v) {
    unsigned r;
    asm("cvt.rn.f16x2.e4m3x2 %0, %1;" : "=r"(r) : "h"((unsigned short)v));
    return *reinterpret_cast<__half2*>(&r);
}

__device__ __forceinline__ void stage_us2(char* stg, int rloc, int c, unsigned short u) {
    *reinterpret_cast<unsigned short*>(stg + rloc * 272 + c) = u;
}
__device__ __forceinline__ void flush512(const char* stg, unsigned char* gdst, int row0,
                                         int tid, int nmax) {
    int fr = tid >> 2, q = tid & 3;
    int gr = row0 + fr;
    if (gr < nmax) {
        uint4 v0 = *reinterpret_cast<const uint4*>(stg + fr * 272 + q * 32);
        uint4 v1 = *reinterpret_cast<const uint4*>(stg + fr * 272 + q * 32 + 16);
        *reinterpret_cast<uint4*>(gdst + (size_t)gr * 128 + q * 32) = v0;
        *reinterpret_cast<uint4*>(gdst + (size_t)gr * 128 + q * 32 + 16) = v1;
    }
}

// ---------------- prologue kernels ----------------

__global__ void u_kernel(const float* __restrict__ w1, const float* __restrict__ b1) {
    __shared__ float srbf[GNUM][64];
    int l = blockIdx.y, g0 = blockIdx.x * 64, f = threadIdx.x;
    float wreg[GNUM];
    #pragma unroll
    for (int j = 0; j < GNUM; j++) wreg[j] = w1[l * GNUM * HD + j * HD + f];
    const float DELTA = 10.f / 49.f;
    const float COEFF = -0.5f / (DELTA * DELTA);
    for (int i = f; i < 64 * GNUM; i += 128) {
        int j = i >> 6, g = i & 63;
        float d = (g0 + g) * HGRID;
        float u = d - j * DELTA;
        srbf[j][g] = __expf(COEFF * u * u);
    }
    __syncthreads();
    float sb = b1[l * HD + f];
    #pragma unroll 1
    for (int gt = 0; gt < 8; gt++) {
        float acc[8];
        #pragma unroll
        for (int q = 0; q < 8; q++) acc[q] = sb;
        #pragma unroll
        for (int j = 0; j < GNUM; j++) {
            const float4* p = reinterpret_cast<const float4*>(&srbf[j][gt * 8]);
            float4 r0 = p[0], r1 = p[1];
            acc[0] = fmaf(r0.x, wreg[j], acc[0]);
            acc[1] = fmaf(r0.y, wreg[j], acc[1]);
            acc[2] = fmaf(r0.z, wreg[j], acc[2]);
            acc[3] = fmaf(r0.w, wreg[j], acc[3]);
            acc[4] = fmaf(r1.x, wreg[j], acc[4]);
            acc[5] = fmaf(r1.y, wreg[j], acc[5]);
            acc[6] = fmaf(r1.z, wreg[j], acc[6]);
            acc[7] = fmaf(r1.w, wreg[j], acc[7]);
        }
        #pragma unroll
        for (int q = 0; q < 8; q++)
            g_U[((size_t)l * TPTS + g0 + gt * 8 + q) * HD + f] = __float2bfloat16(sspf(acc[q]));
    }
}

__global__ void wconv_kernel(const float* __restrict__ w1,
                             const float* __restrict__ w2,
                             const float* __restrict__ wi,
                             const float* __restrict__ m2) {
    int t = blockIdx.x * blockDim.x + threadIdx.x;
    const int per = LNUM * HD * HD;
    if (t >= 4 * per) return;
    int a = t / per, r = t - a * per;
    int l = r >> 14, q = r & 16383, n = q >> 7, k = q & 127;
    const float* src = (a == 0) ? w1 : (a == 1) ? w2 : (a == 2) ? wi : m2;
    float v = src[(l << 14) + (k << 7) + n];
    __nv_bfloat16* dst = (a == 0) ? g_wT1 : (a == 1) ? g_wT2 : (a == 2) ? g_wTi : g_wM2;
    dst[r] = __float2bfloat16(v);
}

// table8 = e4m3( (U @ w2 + b2) * C(d) * ST ) — 512 threads, N-split warps
__global__ __launch_bounds__(512, 2) void tableg_kernel(const float* __restrict__ b2) {
    extern __shared__ __nv_bfloat16 sm[];
    __nv_bfloat16* As = sm;
    __nv_bfloat16* Bs = sm + 128 * TILE_STRIDE;
    int tid = threadIdx.x;
    int warp = tid >> 5, lane = tid & 31, g = lane >> 2, t = lane & 3;
    int wm = warp & 7, wn = warp >> 3;
    int mo = wm * 16, nbase = wn * 64;
    int l = blockIdx.y, row0 = blockIdx.x * 128;
    unsigned sA = (unsigned)__cvta_generic_to_shared(As);
    unsigned sB = (unsigned)__cvta_generic_to_shared(Bs);
    cpa_fill512(sA, g_U + ((size_t)l * TPTS + row0) * HD, tid);
    cpa_fill512(sB, g_wM2 + l * HD * HD, tid);
    cpa_commit();
    cpa_wait<0>();
    __syncthreads();
    float acc[8][4];
    #pragma unroll
    for (int nt = 0; nt < 8; nt++) { acc[nt][0]=acc[nt][1]=acc[nt][2]=acc[nt][3]=0.f; }
    mma_half(sA, sB, mo, nbase, lane, acc);
    __syncthreads();
    int r1 = row0 + mo + g, r2 = r1 + 8;
    float C1 = 0.5f * (__cosf(r1 * HGRID * 0.3141592653589793f) + 1.f) * ST;
    float C2 = 0.5f * (__cosf(r2 * HGRID * 0.3141592653589793f) + 1.f) * ST;
    char* stg = reinterpret_cast<char*>(As);
    #pragma unroll
    for (int nt = 0; nt < 8; nt++) {
        int c = nbase + nt * 8 + 2 * t;
        float bb0 = b2[l * HD + c], bb1 = b2[l * HD + c + 1];
        stage_us2(stg, mo + g,     c, e4m3x2_from_f2((acc[nt][0]+bb0)*C1, (acc[nt][1]+bb1)*C1));
        stage_us2(stg, mo + g + 8, c, e4m3x2_from_f2((acc[nt][2]+bb0)*C2, (acc[nt][3]+bb1)*C2));
    }
    __syncthreads();
    flush512(stg, g_t8 + (size_t)l * TPTS * HD, row0, tid, TPTS);
}

// x8 = e4m3( (emb[z] @ lin1_w[0]) * SX ), also g_h = emb[z]. 512 threads.
__global__ __launch_bounds__(512, 2) void lin1embed_kernel(const int* __restrict__ z,
                                                           const float* __restrict__ emb) {
    extern __shared__ __nv_bfloat16 sm[];
    __nv_bfloat16* As = sm;
    __nv_bfloat16* Bs = sm + 128 * TILE_STRIDE;
    int tid = threadIdx.x;
    int warp = tid >> 5, lane = tid & 31, g = lane >> 2, t = lane & 3;
    int wm = warp & 7, wn = warp >> 3;
    int mo = wm * 16, nbase = wn * 64;
    int row0 = blockIdx.x * 128;
    unsigned sA = (unsigned)__cvta_generic_to_shared(As);
    unsigned sB = (unsigned)__cvta_generic_to_shared(Bs);
    cpa_fill512(sB, g_wT1, tid);
    cpa_commit();
    {   // emb gather: 4 threads/row, each 32 fp32 cols
        int r = tid >> 2, q = tid & 3;
        int gr = row0 + r;
        __nv_bfloat16* dstA = As + r * TILE_STRIDE + q * 32;
        if (gr < NATOMS) {
            int zr = z[gr];
            const float4* p = reinterpret_cast<const float4*>(emb + zr * HD + q * 32);
            float4 v[8];
            #pragma unroll
            for (int j = 0; j < 8; j++) v[j] = p[j];
            float4* dh = reinterpret_cast<float4*>(g_h + (size_t)gr * HD + q * 32);
            #pragma unroll
            for (int j = 0; j < 8; j++) {
                dh[j] = v[j];
                uint2 st;
                st.x = pack_bf16x2(v[j].x, v[j].y);
                st.y = pack_bf16x2(v[j].z, v[j].w);
                *reinterpret_cast<uint2*>(dstA + j * 4) = st;
            }
        } else {
            #pragma unroll
            for (int j = 0; j < 8; j++)
                *reinterpret_cast<uint2*>(dstA + j * 4) = make_uint2(0u, 0u);
        }
    }
    cpa_wait<0>();
    __syncthreads();
    float acc[8][4];
    #pragma unroll
    for (int nt = 0; nt < 8; nt++) { acc[nt][0]=acc[nt][1]=acc[nt][2]=acc[nt][3]=0.f; }
    mma_half(sA, sB, mo, nbase, lane, acc);
    __syncthreads();
    char* stg = reinterpret_cast<char*>(As);
    #pragma unroll
    for (int nt = 0; nt < 8; nt++) {
        int c = nbase + nt * 8 + 2 * t;
        stage_us2(stg, mo + g,     c, e4m3x2_from_f2(acc[nt][0]*SX, acc[nt][1]*SX));
        stage_us2(stg, mo + g + 8, c, e4m3x2_from_f2(acc[nt][2]*SX, acc[nt][3]*SX));
    }
    __syncthreads();
    flush512(stg, g_x8, row0, tid, NATOMS);
}

__global__ void eprep_kernel(const float* __restrict__ pos, const int* __restrict__ col) {
    int e = blockIdx.x * blockDim.x + threadIdx.x;
    if (e >= EDGES) return;
    int r = e >> 5;
    int c = col[e];
    float dx = pos[3*r]   - pos[3*c];
    float dy = pos[3*r+1] - pos[3*c+1];
    float dz = pos[3*r+2] - pos[3*c+2];
    float d = sqrtf(fmaf(dx, dx, fmaf(dy, dy, dz * dz)));
    int gi = __float2int_rn(d * (1.0f / HGRID));
    gi = max(0, min(TPTS - 1, gi));
    g_gi[e] = (unsigned short)gi;
}

// ---------------- per-layer kernels ----------------

// High-occupancy standalone edge gather (saturates L2).
__global__ void edge_agg_kernel(const int* __restrict__ col, int l) {
    int warp = threadIdx.x >> 5, lane = threadIdx.x & 31;
    int atom = blockIdx.x * 8 + warp;
    if (atom >= NATOMS) return;
    int base = atom * KNBR;
    int cIdx = col[base + lane];
    int gIdx = (int)g_gi[base + lane];
    const unsigned char* tab = g_t8 + (size_t)l * TPTS * HD;
    __half2 a01 = __floats2half2_rn(0.f, 0.f);
    __half2 a23 = __floats2half2_rn(0.f, 0.f);
    int off = lane * 4;
    #pragma unroll 8
    for (int k = 0; k < KNBR; k++) {
        int c  = __shfl_sync(0xffffffffu, cIdx, k);
        int gg = __shfl_sync(0xffffffffu, gIdx, k);
        unsigned xw = *reinterpret_cast<const unsigned*>(g_x8 + c * HD + off);
        unsigned tw = *reinterpret_cast<const unsigned*>(tab + gg * HD + off);
        a01 = __hfma2(e4m3x2_to_h2(xw), e4m3x2_to_h2(tw), a01);
        a23 = __hfma2(e4m3x2_to_h2(xw >> 16), e4m3x2_to_h2(tw >> 16), a23);
    }
    float2 f01 = __half22float2(a01);
    float2 f23 = __half22float2(a23);
    uint2 out;
    out.x = pack_bf16x2(f01.x * INV_SXT, f01.y * INV_SXT);
    out.y = pack_bf16x2(f23.x * INV_SXT, f23.y * INV_SXT);
    *reinterpret_cast<uint2*>(&g_agg[atom * HD + off]) = out;
}

// h += ssp(agg @ lin2 + b2) @ int_lin + bi ; x8 = e4m3(h_new @ W1[l+1] * SX). 512 threads.
// cp.async groups split so stage 1 doesn't wait on Wi, stage 2 doesn't wait on W1next.
__global__ __launch_bounds__(512, 2) void fusedX_kernel(int l, const float* __restrict__ b2,
                                                        const float* __restrict__ bi) {
    extern __shared__ __nv_bfloat16 sm[];
    __nv_bfloat16* As  = sm;
    __nv_bfloat16* Bs  = sm + 128 * TILE_STRIDE;
    __nv_bfloat16* Bs2 = sm + 2 * 128 * TILE_STRIDE;
    int tid = threadIdx.x;
    int warp = tid >> 5, lane = tid & 31, g = lane >> 2, t = lane & 3;
    int wm = warp & 7, wn = warp >> 3;
    int mo = wm * 16, nbase = wn * 64;
    int row0 = blockIdx.x * 128;
    unsigned sA  = (unsigned)__cvta_generic_to_shared(As);
    unsigned sB  = (unsigned)__cvta_generic_to_shared(Bs);
    unsigned sB2 = (unsigned)__cvta_generic_to_shared(Bs2);
    // group0: As (agg, zfill-guarded) + Bs (W2)
    {
        int r = tid >> 2, q = tid & 3;
        int gr = row0 + r;
        unsigned sz = (gr < NATOMS) ? 16u : 0u;
        const char* srcA = (const char*)(g_agg + (size_t)(gr < NATOMS ? gr : 0) * HD) + q * 64;
        unsigned dA = sA + (unsigned)(r * 272 + q * 64);
        #pragma unroll
        for (int j = 0; j < 4; j++) cpa16(dA + j * 16, srcA + j * 16, sz);
    }
    cpa_fill512(sB, g_wT2 + l * HD * HD, tid);
    cpa_commit();
    // group1: Bs2 (Wi) — lands during stage-1 mma
    cpa_fill512(sB2, g_wTi + l * HD * HD, tid);
    cpa_commit();
    cpa_wait<1>();             // group0 done (Wi may still be in flight)
    __syncthreads();
    float acc[8][4];
    #pragma unroll
    for (int nt = 0; nt < 8; nt++) { acc[nt][0]=acc[nt][1]=acc[nt][2]=acc[nt][3]=0.f; }
    // ---- stage 1: agg @ lin2 ----
    mma_half(sA, sB, mo, nbase, lane, acc);
    __syncthreads();           // all warps done reading As + Bs
    // ssp(+bias) -> As
    #pragma unroll
    for (int nt = 0; nt < 8; nt++) {
        int c = nbase + nt * 8 + 2 * t;
        float v0 = sspf(acc[nt][0] + b2[c]);
        float v1 = sspf(acc[nt][1] + b2[c + 1]);
        float v2 = sspf(acc[nt][2] + b2[c]);
        float v3 = sspf(acc[nt][3] + b2[c + 1]);
        *reinterpret_cast<unsigned*>(&As[(mo+g)  *TILE_STRIDE + c]) = pack_bf16x2(v0, v1);
        *reinterpret_cast<unsigned*>(&As[(mo+g+8)*TILE_STRIDE + c]) = pack_bf16x2(v2, v3);
    }
    __syncthreads();
    // group2: W1next streams in during stage 2 (commit unconditionally so wait counts are exact)
    if (l < LNUM - 1) cpa_fill512(sB, g_wT1 + (l + 1) * HD * HD, tid);
    cpa_commit();
    cpa_wait<1>();             // group1 (Wi) done; group2 may be pending
    __syncthreads();
    // ---- stage 2: t @ int_lin ----
    #pragma unroll
    for (int nt = 0; nt < 8; nt++) { acc[nt][0]=acc[nt][1]=acc[nt][2]=acc[nt][3]=0.f; }
    mma_half(sA, sB2, mo, nbase, lane, acc);
    __syncthreads();           // all warps done reading As before rewriting it
    int r1 = row0 + mo + g, r2 = r1 + 8;
    #pragma unroll
    for (int nt = 0; nt < 8; nt++) {
        int c = nbase + nt * 8 + 2 * t;
        float bb0 = bi[c], bb1 = bi[c + 1];
        if (r1 < NATOMS) {
            float2 hv = *reinterpret_cast<float2*>(&g_h[r1 * HD + c]);
            hv.x += acc[nt][0] + bb0;
            hv.y += acc[nt][1] + bb1;
            *reinterpret_cast<float2*>(&g_h[r1 * HD + c]) = hv;
            *reinterpret_cast<unsigned*>(&As[(mo+g)*TILE_STRIDE + c]) = pack_bf16x2(hv.x, hv.y);
        } else {
            *reinterpret_cast<unsigned*>(&As[(mo+g)*TILE_STRIDE + c]) = 0u;
        }
        if (r2 < NATOMS) {
            float2 hv = *reinterpret_cast<float2*>(&g_h[r2 * HD + c]);
            hv.x += acc[nt][2] + bb0;
            hv.y += acc[nt][3] + bb1;
            *reinterpret_cast<float2*>(&g_h[r2 * HD + c]) = hv;
            *reinterpret_cast<unsigned*>(&As[(mo+g+8)*TILE_STRIDE + c]) = pack_bf16x2(hv.x, hv.y);
        } else {
            *reinterpret_cast<unsigned*>(&As[(mo+g+8)*TILE_STRIDE + c]) = 0u;
        }
    }
    cpa_wait<0>();             // W1next complete (empty group on last layer)
    if (l >= LNUM - 1) return;
    __syncthreads();           // As writes + Bs(W1next) visible to all
    // ---- stage 3: x8 = h_new @ W1[l+1] ----
    #pragma unroll
    for (int nt = 0; nt < 8; nt++) { acc[nt][0]=acc[nt][1]=acc[nt][2]=acc[nt][3]=0.f; }
    mma_half(sA, sB, mo, nbase, lane, acc);
    __syncthreads();           // all warps done reading As before staging
    char* stg = reinterpret_cast<char*>(As);
    #pragma unroll
    for (int nt = 0; nt < 8; nt++) {
        int c = nbase + nt * 8 + 2 * t;
        stage_us2(stg, mo + g,     c, e4m3x2_from_f2(acc[nt][0]*SX, acc[nt][1]*SX));
        stage_us2(stg, mo + g + 8, c, e4m3x2_from_f2(acc[nt][2]*SX, acc[nt][3]*SX));
    }
    __syncthreads();
    flush512(stg, g_x8, row0, tid, NATOMS);
}

// ---------------- head ----------------
__global__ void head_kernel(const float* __restrict__ w1, const float* __restrict__ b1, const float* __restrict__ a1p,
                            const float* __restrict__ w2, const float* __restrict__ b2, const float* __restrict__ a2p,
                            const float* __restrict__ w3, const float* __restrict__ b3,
                            float* __restrict__ out) {
    int warp = threadIdx.x >> 5, lane = threadIdx.x & 31;
    int atom = blockIdx.x * 8 + warp;
    if (atom >= NATOMS) return;
    float hh[4];
    #pragma unroll
    for (int q = 0; q < 4; q++) hh[q] = g_h[atom * HD + q * 32 + lane];
    float s1a = b1[lane], s1b = b1[lane + 32];
    #pragma unroll
    for (int q = 0; q < 4; q++) {
        #pragma unroll 8
        for (int k2 = 0; k2 < 32; k2++) {
            float hv = __shfl_sync(0xffffffffu, hh[q], k2);
            int k = q * 32 + k2;
            s1a = fmaf(hv, w1[k * 64 + lane], s1a);
            s1b = fmaf(hv, w1[k * 64 + lane + 32], s1b);
        }
    }
    float A1 = a1p[0];
    float t1a = (s1a >= 0.f) ? s1a : A1 * s1a;
    float t1b = (s1b >= 0.f) ? s1b : A1 * s1b;
    float s2 = b2[lane];
    #pragma unroll
    for (int q = 0; q < 2; q++) {
        float src = q ? t1b : t1a;
        #pragma unroll 8
        for (int j2 = 0; j2 < 32; j2++) {
            float tv = __shfl_sync(0xffffffffu, src, j2);
            s2 = fmaf(tv, w2[(q * 32 + j2) * 32 + lane], s2);
        }
    }
    float A2 = a2p[0];
    float t2 = (s2 >= 0.f) ? s2 : A2 * s2;
    float p = t2 * w3[lane];
    #pragma unroll
    for (int o = 16; o > 0; o >>= 1) p += __shfl_xor_sync(0xffffffffu, p, o);
    if (lane == 0) out[atom] = p + b3[0];
}

// ---------------- launch ----------------
extern "C" void kernel_launch(void* const* d_in, const int* in_sizes, int n_in,
                              void* d_out, int out_size) {
    const int*   z    = (const int*)  d_in[0];
    const float* pos  = (const float*)d_in[1];
    const int*   eidx = (const int*)  d_in[2];
    const float* emb  = (const float*)d_in[3];
    const float* mw1  = (const float*)d_in[4];
    const float* mb1  = (const float*)d_in[5];
    const float* mw2  = (const float*)d_in[6];
    const float* mb2  = (const float*)d_in[7];
    const float* l1w  = (const float*)d_in[8];
    const float* l2w  = (const float*)d_in[9];
    const float* l2b  = (const float*)d_in[10];
    const float* ilw  = (const float*)d_in[11];
    const float* ilb  = (const float*)d_in[12];
    const float* hw1  = (const float*)d_in[13];
    const float* hb1  = (const float*)d_in[14];
    const float* ha1  = (const float*)d_in[15];
    const float* hw2  = (const float*)d_in[16];
    const float* hb2  = (const float*)d_in[17];
    const float* ha2  = (const float*)d_in[18];
    const float* hw3  = (const float*)d_in[19];
    const float* hb3  = (const float*)d_in[20];
    const int*   col  = eidx + EDGES;
    float*       out  = (float*)d_out;

    static int smem_set = 0;
    if (!smem_set) {
        cudaFuncSetAttribute(lin1embed_kernel, cudaFuncAttributeMaxDynamicSharedMemorySize, SMEM_2T);
        cudaFuncSetAttribute(tableg_kernel,    cudaFuncAttributeMaxDynamicSharedMemorySize, SMEM_2T);
        cudaFuncSetAttribute(fusedX_kernel,    cudaFuncAttributeMaxDynamicSharedMemorySize, SMEM_3T);
        smem_set = 1;
    }

    int gemm_blocks = (NATOMS + 127) / 128;
    int atom_blocks = (NATOMS + 7) / 8;

    // ncu capture (4th launch) stays on lin1embed.
    u_kernel<<<dim3(TPTS / 64, LNUM), 128>>>(mw1, mb1);                          // 0
    wconv_kernel<<<(4 * LNUM * HD * HD + 255) / 256, 256>>>(l1w, l2w, ilw, mw2); // 1
    tableg_kernel<<<dim3(TPTS / 128, LNUM), 512, SMEM_2T>>>(mb2);                // 2
    lin1embed_kernel<<<gemm_blocks, 512, SMEM_2T>>>(z, emb);                     // 3  <-- profiled
    eprep_kernel<<<(EDGES + 255) / 256, 256>>>(pos, col);                        // 4

    for (int l = 0; l < LNUM; l++) {
        edge_agg_kernel<<<atom_blocks, 256>>>(col, l);
        fusedX_kernel<<<gemm_blocks, 512, SMEM_3T>>>(l, l2b + l * HD, ilb + l * HD);
    }
    head_kernel<<<atom_blocks, 256>>>(hw1, hb1, ha1, hw2, hb2, ha2, hw3, hb3, out);
}